// round 8
// baseline (speedup 1.0000x reference)
#include <cuda_runtime.h>

#define BATCH 4096
#define FEAT  512
#define NUMC  10000

#define BLOCK_THREADS 256
#define WARPS_PER_BLOCK (BLOCK_THREADS / 32)        // 8
#define GRID_BLOCKS (BATCH / WARPS_PER_BLOCK)       // 512

#define FIX_SCALE 67108864.0                        // 2^26 (Q.26 fixed point)
#define CNT_SHIFT 53
#define SUM_MASK  ((1ULL << CNT_SHIFT) - 1ULL)

// Scratch (no cudaMalloc allowed). Zero-init; reset by the last block each run.
// bits [0,53)  = Q.26 fixed-point sum (max ~2^48; integer adds commutative)
// bits [53,64) = completed-block counter (512 * 2^53 = 2^62 < 2^64)
__device__ unsigned long long g_isum;

__global__ void __launch_bounds__(BLOCK_THREADS)
center_loss_kernel(const float* __restrict__ x,
                   const int*   __restrict__ labels32,
                   const float* __restrict__ centers,
                   float*       __restrict__ out) {
    const int lane = threadIdx.x & 31;
    const int wid  = threadIdx.x >> 5;
    const int row  = blockIdx.x * WARPS_PER_BLOCK + wid;

    // ---- epoch 1: ALL loads issued before any dependent select ---------------
    // dtype probe: odd words of first 64 int32 all zero <=> int64 labels.
    // P(false positive for int32 labels) = 1e-128. Fixed probe, every warp.
    int probe = __ldg(&labels32[2 * lane + 1]);
    int labA  = __ldg(&labels32[2 * row]);    // int64 interpretation (low word)
    int labB  = __ldg(&labels32[row]);        // int32 interpretation

    // Clamp BOTH candidates: the wrong-path one may be garbage (labA reads
    // beyond a 16KB int32 buffer for row>=2048). Keeps speculative gathers
    // in-bounds; the wrong path's result is discarded after the ballot.
    labA = min(max(labA, 0), NUMC - 1);
    labB = min(max(labB, 0), NUMC - 1);

    const float4* xr  = reinterpret_cast<const float4*>(x + (size_t)row * FEAT);
    const float4* crA = reinterpret_cast<const float4*>(centers + (size_t)labA * FEAT);
    const float4* crB = reinterpret_cast<const float4*>(centers + (size_t)labB * FEAT);

    float4 xv[4], cA[4], cB[4];
#pragma unroll
    for (int i = 0; i < 4; i++) xv[i] = __ldg(&xr[lane + 32 * i]);
#pragma unroll
    for (int i = 0; i < 4; i++) cA[i] = __ldg(&crA[lane + 32 * i]);
#pragma unroll
    for (int i = 0; i < 4; i++) cB[i] = __ldg(&crB[lane + 32 * i]);

    // dtype resolution happens while loads are in flight
    bool is64 = (__ballot_sync(0xffffffffu, probe != 0) == 0u);

    // ---- compute BOTH distances, select the scalar --------------------------
    float sA0 = 0.f, sA1 = 0.f, sB0 = 0.f, sB1 = 0.f;
#pragma unroll
    for (int i = 0; i < 4; i++) {
        float d;
        d = xv[i].x - cA[i].x; sA0 = fmaf(d, d, sA0);
        d = xv[i].y - cA[i].y; sA1 = fmaf(d, d, sA1);
        d = xv[i].z - cA[i].z; sA0 = fmaf(d, d, sA0);
        d = xv[i].w - cA[i].w; sA1 = fmaf(d, d, sA1);
        d = xv[i].x - cB[i].x; sB0 = fmaf(d, d, sB0);
        d = xv[i].y - cB[i].y; sB1 = fmaf(d, d, sB1);
        d = xv[i].z - cB[i].z; sB0 = fmaf(d, d, sB0);
        d = xv[i].w - cB[i].w; sB1 = fmaf(d, d, sB1);
    }
    float acc = is64 ? (sA0 + sA1) : (sB0 + sB1);

#pragma unroll
    for (int o = 16; o > 0; o >>= 1)
        acc += __shfl_xor_sync(0xffffffffu, acc, o);

    __shared__ float sh[WARPS_PER_BLOCK];
    if (lane == 0)
        sh[wid] = fminf(fmaxf(acc, 1e-12f), 1e12f);   // clip diagonal entry
    __syncthreads();

    if (threadIdx.x == 0) {
        // fixed-order deterministic block sum (8 values)
        float bs = 0.0f;
#pragma unroll
        for (int w = 0; w < WARPS_PER_BLOCK; w++) bs += sh[w];

        // ONE atomic: accumulate Q.26 sum AND bump the block counter.
        unsigned long long q =
            (unsigned long long)__double2ll_rn((double)bs * FIX_SCALE);
        unsigned long long old =
            atomicAdd(&g_isum, q + (1ULL << CNT_SHIFT));

        if ((old >> CNT_SHIFT) == (unsigned long long)(GRID_BLOCKS - 1)) {
            // 512th arrival: grand total already in hand — no read-back.
            unsigned long long tot = (old & SUM_MASK) + q;
            double t = (double)tot * (1.0 / FIX_SCALE);
            out[0] = (float)(t / (double)BATCH + (double)(NUMC - 1) * 1e-12);
            g_isum = 0ULL;   // replay-safe reset (all contributions landed)
        }
    }
}

extern "C" void kernel_launch(void* const* d_in, const int* in_sizes, int n_in,
                              void* d_out, int out_size) {
    const float* x       = (const float*)d_in[0];
    const int*   labels  = (const int*)  d_in[1];
    const float* centers = (const float*)d_in[2];
    float*       out     = (float*)d_out;

    center_loss_kernel<<<GRID_BLOCKS, BLOCK_THREADS>>>(x, labels, centers, out);
}